// round 3
// baseline (speedup 1.0000x reference)
#include <cuda_runtime.h>

// Problem constants (fixed for this dataset)
#define BB   4
#define CC   128
#define HH   128
#define WW   128
#define GG   4
#define GCH  32      // channels per group
#define PP   9       // K*K taps
#define NOFF 72      // G*P*2
#define NMSK 36      // G*P
#define TILE 32      // pixels per block
#define NTHR 256

// overlay buffer: phase 0/1 use it as xs[TILE][CC] (16384 B);
// phase 2.5/3 use it as swt[TILE][NMSK] float4 (18432 B) + slin[TILE][NMSK] int (4608 B)
#define UBUF_BYTES (TILE * NMSK * 16 + TILE * NMSK * 4)   // 23040

__global__ __launch_bounds__(NTHR) void dcnv3_fused(
    const float* __restrict__ in,     // (B,H,W,C) channel-last (view of (B,C,H,W))
    const float* __restrict__ Woff,   // (C, 72) row-major
    const float* __restrict__ boff,   // (72)
    const float* __restrict__ Wmask,  // (C, 36) row-major
    const float* __restrict__ bmask,  // (36)
    float* __restrict__ out)          // (B,H,W,C) channel-last
{
    __shared__ __align__(16) char ubuf[UBUF_BYTES];   // 22.5 KB (xs | swt+slin)
    __shared__ float offs[TILE][NOFF];                // 9 KB
    __shared__ float msk[TILE][NMSK];                 // 4.5 KB

    float (*xs)[CC]        = reinterpret_cast<float(*)[CC]>(ubuf);
    float4 (*swt)[NMSK]    = reinterpret_cast<float4(*)[NMSK]>(ubuf);
    int (*slin)[NMSK]      = reinterpret_cast<int(*)[NMSK]>(ubuf + TILE * NMSK * 16);

    const int tid = threadIdx.x;
    const int blk = blockIdx.x;
    const int wt = blk % (WW / TILE);
    const int h  = (blk / (WW / TILE)) % HH;
    const int b  = blk / ((WW / TILE) * HH);
    const int w0 = wt * TILE;

    // ---- phase 0: load the 32 pixels' features (contiguous 32*128 floats) ----
    const float4* xbase4 = reinterpret_cast<const float4*>(
        in + (((size_t)b * HH + h) * WW + w0) * CC);
    float4* xs4 = reinterpret_cast<float4*>(&xs[0][0]);
    #pragma unroll
    for (int i = tid; i < TILE * CC / 4; i += NTHR) xs4[i] = xbase4[i];
    __syncthreads();

    // ---- phase 1: register-tiled matvec. 4 pixels x 4 outputs per thread.
    // lane map: jq = tid>>3 (27 j-quads), pg = tid&7 (8 groups of 4 pixels).
    // A warp holds only 4 adjacent j-quads -> W LDG.128 hits ~1 cache line.
    if (tid < 216) {
        const int jq = tid >> 3;             // 0..26
        const int pg = tid & 7;              // 0..7
        const int p0 = pg * 4;
        const bool is_off = (jq < 18);
        const int j0 = is_off ? jq * 4 : (jq - 18) * 4;
        const float4* W4 = reinterpret_cast<const float4*>(
            (is_off ? Woff : Wmask) + j0);
        const int ws4 = (is_off ? NOFF : NMSK) / 4;   // row stride in float4
        const float* bias = is_off ? boff : bmask;

        float4 acc0 = make_float4(0.f, 0.f, 0.f, 0.f);
        float4 acc1 = make_float4(0.f, 0.f, 0.f, 0.f);
        float4 acc2 = make_float4(0.f, 0.f, 0.f, 0.f);
        float4 acc3 = make_float4(0.f, 0.f, 0.f, 0.f);
        const float4* x0p = reinterpret_cast<const float4*>(xs[p0 + 0]);
        const float4* x1p = reinterpret_cast<const float4*>(xs[p0 + 1]);
        const float4* x2p = reinterpret_cast<const float4*>(xs[p0 + 2]);
        const float4* x3p = reinterpret_cast<const float4*>(xs[p0 + 3]);

        #pragma unroll 4
        for (int k4 = 0; k4 < CC / 4; k4++) {
            const float4 xa = x0p[k4];
            const float4 xb = x1p[k4];
            const float4 xc = x2p[k4];
            const float4 xd = x3p[k4];
            const float xav[4] = { xa.x, xa.y, xa.z, xa.w };
            const float xbv[4] = { xb.x, xb.y, xb.z, xb.w };
            const float xcv[4] = { xc.x, xc.y, xc.z, xc.w };
            const float xdv[4] = { xd.x, xd.y, xd.z, xd.w };
            #pragma unroll
            for (int kk = 0; kk < 4; kk++) {
                const float4 w = W4[(k4 * 4 + kk) * ws4];
                acc0.x = fmaf(xav[kk], w.x, acc0.x);
                acc0.y = fmaf(xav[kk], w.y, acc0.y);
                acc0.z = fmaf(xav[kk], w.z, acc0.z);
                acc0.w = fmaf(xav[kk], w.w, acc0.w);
                acc1.x = fmaf(xbv[kk], w.x, acc1.x);
                acc1.y = fmaf(xbv[kk], w.y, acc1.y);
                acc1.z = fmaf(xbv[kk], w.z, acc1.z);
                acc1.w = fmaf(xbv[kk], w.w, acc1.w);
                acc2.x = fmaf(xcv[kk], w.x, acc2.x);
                acc2.y = fmaf(xcv[kk], w.y, acc2.y);
                acc2.z = fmaf(xcv[kk], w.z, acc2.z);
                acc2.w = fmaf(xcv[kk], w.w, acc2.w);
                acc3.x = fmaf(xdv[kk], w.x, acc3.x);
                acc3.y = fmaf(xdv[kk], w.y, acc3.y);
                acc3.z = fmaf(xdv[kk], w.z, acc3.z);
                acc3.w = fmaf(xdv[kk], w.w, acc3.w);
            }
        }
        const float4 bv = *reinterpret_cast<const float4*>(bias + j0);
        acc0.x += bv.x; acc0.y += bv.y; acc0.z += bv.z; acc0.w += bv.w;
        acc1.x += bv.x; acc1.y += bv.y; acc1.z += bv.z; acc1.w += bv.w;
        acc2.x += bv.x; acc2.y += bv.y; acc2.z += bv.z; acc2.w += bv.w;
        acc3.x += bv.x; acc3.y += bv.y; acc3.z += bv.z; acc3.w += bv.w;

        if (is_off) {
            *reinterpret_cast<float4*>(&offs[p0 + 0][j0]) = acc0;
            *reinterpret_cast<float4*>(&offs[p0 + 1][j0]) = acc1;
            *reinterpret_cast<float4*>(&offs[p0 + 2][j0]) = acc2;
            *reinterpret_cast<float4*>(&offs[p0 + 3][j0]) = acc3;
        } else {
            *reinterpret_cast<float4*>(&msk[p0 + 0][j0]) = acc0;
            *reinterpret_cast<float4*>(&msk[p0 + 1][j0]) = acc1;
            *reinterpret_cast<float4*>(&msk[p0 + 2][j0]) = acc2;
            *reinterpret_cast<float4*>(&msk[p0 + 3][j0]) = acc3;
        }
    }
    __syncthreads();

    // ---- phase 2: softmax over the 9 taps per (pixel, group) ----
    if (tid < TILE * GG) {
        const int pp = tid / GG, g = tid % GG;
        float* m = &msk[pp][g * PP];
        float mx = m[0];
        #pragma unroll
        for (int p = 1; p < PP; p++) mx = fmaxf(mx, m[p]);
        float e[PP], s = 0.f;
        #pragma unroll
        for (int p = 0; p < PP; p++) { e[p] = __expf(m[p] - mx); s += e[p]; }
        const float inv = 1.f / s;
        #pragma unroll
        for (int p = 0; p < PP; p++) m[p] = e[p] * inv;
    }
    __syncthreads();

    // ---- phase 2.5: per-(pixel,g,p) packed corner base + mask-folded weights ----
    // (overwrites xs; safe, xs is dead after phase 1)
    for (int idx = tid; idx < TILE * NMSK; idx += NTHR) {
        const int pp = idx / NMSK;
        const int gp = idx % NMSK;
        const int p  = gp % PP;
        const float dx = offs[pp][gp * 2 + 0];
        const float dy = offs[pp][gp * 2 + 1];
        // padded coords: px = w + p/3 + dx ; py = h + p%3 + dy
        const float px = (float)(w0 + pp) + (float)(p / 3) + dx;
        const float py = (float)h + (float)(p % 3) + dy;
        const float x0f = floorf(px), y0f = floorf(py);
        const float tx = px - x0f, ty = py - y0f;
        const int ix0 = (int)x0f, iy0 = (int)y0f;
        const float m = msk[pp][gp];

        float w00 = (1.f - tx) * (1.f - ty) * m;
        float w10 = tx * (1.f - ty) * m;
        float w01 = (1.f - tx) * ty * m;
        float w11 = tx * ty * m;
        // zero out-of-range corners (padded coord must be in [1,128])
        const bool vx0 = ((unsigned)(ix0 - 1) < (unsigned)WW);
        const bool vx1 = ((unsigned)(ix0)     < (unsigned)WW);
        const bool vy0 = ((unsigned)(iy0 - 1) < (unsigned)HH);
        const bool vy1 = ((unsigned)(iy0)     < (unsigned)HH);
        if (!(vx0 && vy0)) w00 = 0.f;
        if (!(vx1 && vy0)) w10 = 0.f;
        if (!(vx0 && vy1)) w01 = 0.f;
        if (!(vx1 && vy1)) w11 = 0.f;

        swt[pp][gp]  = make_float4(w00, w10, w01, w11);
        // linear element index of corner (ix0-1, iy0-1); other corners are
        // at constant offsets +CC, +WW*CC, +CC+WW*CC
        slin[pp][gp] = ((b * HH + (iy0 - 1)) * WW + (ix0 - 1)) * CC;
    }
    __syncthreads();

    // ---- phase 3: gather + accumulate. warp = pixel, lane = float4 channel slot ----
    const int c4 = tid & 31;          // float4 slot -> channels [4*c4, 4*c4+3]
    const int g  = c4 >> 3;           // group of this channel slot
    const float4* in4 = reinterpret_cast<const float4*>(in);
    float4* out4 = reinterpret_cast<float4*>(out);

    #pragma unroll
    for (int pass = 0; pass < 4; pass++) {
        const int pp = (tid >> 5) + pass * 8;
        float4 acc = make_float4(0.f, 0.f, 0.f, 0.f);
        #pragma unroll
        for (int p = 0; p < PP; p++) {
            const int gp = g * PP + p;
            const float4 wv = swt[pp][gp];
            const int base = (slin[pp][gp] >> 2) + c4;   // float4 units
            if (wv.x != 0.f) {
                const float4 v = in4[base];
                acc.x = fmaf(wv.x, v.x, acc.x); acc.y = fmaf(wv.x, v.y, acc.y);
                acc.z = fmaf(wv.x, v.z, acc.z); acc.w = fmaf(wv.x, v.w, acc.w);
            }
            if (wv.y != 0.f) {
                const float4 v = in4[base + (CC / 4)];
                acc.x = fmaf(wv.y, v.x, acc.x); acc.y = fmaf(wv.y, v.y, acc.y);
                acc.z = fmaf(wv.y, v.z, acc.z); acc.w = fmaf(wv.y, v.w, acc.w);
            }
            if (wv.z != 0.f) {
                const float4 v = in4[base + (WW * CC / 4)];
                acc.x = fmaf(wv.z, v.x, acc.x); acc.y = fmaf(wv.z, v.y, acc.y);
                acc.z = fmaf(wv.z, v.z, acc.z); acc.w = fmaf(wv.z, v.w, acc.w);
            }
            if (wv.w != 0.f) {
                const float4 v = in4[base + (WW * CC / 4) + (CC / 4)];
                acc.x = fmaf(wv.w, v.x, acc.x); acc.y = fmaf(wv.w, v.y, acc.y);
                acc.z = fmaf(wv.w, v.z, acc.z); acc.w = fmaf(wv.w, v.w, acc.w);
            }
        }
        const size_t o = (((size_t)b * HH + h) * WW + (w0 + pp)) * (CC / 4) + c4;
        out4[o] = acc;
    }
}

extern "C" void kernel_launch(void* const* d_in, const int* in_sizes, int n_in,
                              void* d_out, int out_size) {
    const float* inp   = (const float*)d_in[0];
    const float* Woff  = (const float*)d_in[1];
    const float* boff  = (const float*)d_in[2];
    const float* Wmask = (const float*)d_in[3];
    const float* bmask = (const float*)d_in[4];
    float* out = (float*)d_out;

    const int nblocks = BB * HH * (WW / TILE);   // 4*128*4 = 2048
    dcnv3_fused<<<nblocks, NTHR>>>(inp, Woff, boff, Wmask, bmask, out);
}

// round 4
// speedup vs baseline: 2.1388x; 2.1388x over previous
#include <cuda_runtime.h>

// Problem constants (fixed for this dataset)
#define BB   4
#define CC   128
#define HH   128
#define WW   128
#define GG   4
#define GCH  32      // channels per group
#define PP   9       // K*K taps
#define NOFF 72      // G*P*2
#define NMSK 36      // G*P
#define TILE 32      // pixels per block
#define NTHR 256
#define ROW  36      // xsT row length in floats (32 px + 4 pad, 16B-aligned)

// overlay buffer: phases 0/1 use it as xsT[CC][ROW] (18432 B);
// phases 2.5/3 use it as swt[TILE][NMSK] float4 (18432 B) + slin[TILE][NMSK] int (4608 B)
#define UBUF_BYTES (TILE * NMSK * 16 + TILE * NMSK * 4)   // 23040

__global__ __launch_bounds__(NTHR) void dcnv3_fused(
    const float* __restrict__ in,     // (B,H,W,C) channel-last (view of (B,C,H,W))
    const float* __restrict__ Woff,   // (C, 72) row-major
    const float* __restrict__ boff,   // (72)
    const float* __restrict__ Wmask,  // (C, 36) row-major
    const float* __restrict__ bmask,  // (36)
    float* __restrict__ out)          // (B,H,W,C) channel-last
{
    __shared__ __align__(16) char ubuf[UBUF_BYTES];   // 22.5 KB (xsT | swt+slin)
    __shared__ float offs[TILE][NOFF];                // 9 KB
    __shared__ float msk[TILE][NMSK];                 // 4.5 KB

    float* xsT          = reinterpret_cast<float*>(ubuf);             // [CC][ROW]
    float4 (*swt)[NMSK] = reinterpret_cast<float4(*)[NMSK]>(ubuf);
    int (*slin)[NMSK]   = reinterpret_cast<int(*)[NMSK]>(ubuf + TILE * NMSK * 16);

    const int tid = threadIdx.x;
    const int blk = blockIdx.x;
    const int wt = blk % (WW / TILE);
    const int h  = (blk / (WW / TILE)) % HH;
    const int b  = blk / ((WW / TILE) * HH);
    const int w0 = wt * TILE;

    // ---- phase 0: load 32 pixels' features and store TRANSPOSED into xsT ----
    // lane groups of 4 do a 4x4 register transpose so STS.128 is conflict-free.
    const float4* xbase4 = reinterpret_cast<const float4*>(
        in + (((size_t)b * HH + h) * WW + w0) * CC);
    const int r = tid & 3;   // element/row index inside 4-lane transpose group
    #pragma unroll
    for (int it = 0; it < 4; it++) {
        const int i  = tid + it * NTHR;      // 0..1023
        const int q  = i >> 7;               // pixel quad 0..7
        const int k4 = (i >> 2) & 31;        // channel quad 0..31
        // load: pixel (4q + r), channels 4k4..4k4+3
        float4 v = xbase4[(q * 4 + r) * (CC / 4) + k4];
        float a0 = v.x, a1 = v.y, a2 = v.z, a3 = v.w;
        // 4x4 transpose across lanes (xor 1 then xor 2)
        {
            float s0 = (r & 1) ? a0 : a1;
            float s1 = (r & 1) ? a2 : a3;
            float g0 = __shfl_xor_sync(0xFFFFFFFF, s0, 1);
            float g1 = __shfl_xor_sync(0xFFFFFFFF, s1, 1);
            if (r & 1) { a0 = g0; a2 = g1; } else { a1 = g0; a3 = g1; }
        }
        {
            float u0 = (r & 2) ? a0 : a2;
            float u1 = (r & 2) ? a1 : a3;
            float h0 = __shfl_xor_sync(0xFFFFFFFF, u0, 2);
            float h1 = __shfl_xor_sync(0xFFFFFFFF, u1, 2);
            if (r & 2) { a0 = h0; a1 = h1; } else { a2 = h0; a3 = h1; }
        }
        // now lane holds channel (4*k4 + r) for pixels 4q..4q+3
        *reinterpret_cast<float4*>(&xsT[(4 * k4 + r) * ROW + 4 * q]) =
            make_float4(a0, a1, a2, a3);
    }
    __syncthreads();

    // ---- phase 1: register-tiled matvec. 4 pixels x 4 outputs per thread.
    // jq = tid>>3 (27 j-quads), pg = tid&7 (8 pixel quads).
    // W LDG.128: 4 adjacent j-quads per warp -> ~1 wavefront (broadcast).
    // x LDS.128: 8 pixel quads cover 128 contiguous bytes -> conflict-free.
    if (tid < 216) {
        const int jq = tid >> 3;             // 0..26
        const int pg = tid & 7;              // 0..7
        const int p0 = pg * 4;
        const bool is_off = (jq < 18);
        const int j0 = is_off ? jq * 4 : (jq - 18) * 4;
        const float* Wb = (is_off ? Woff : Wmask) + j0;
        const int ws = is_off ? NOFF : NMSK;     // row stride in floats
        const float* bias = is_off ? boff : bmask;

        float4 acc0 = make_float4(0.f, 0.f, 0.f, 0.f);
        float4 acc1 = make_float4(0.f, 0.f, 0.f, 0.f);
        float4 acc2 = make_float4(0.f, 0.f, 0.f, 0.f);
        float4 acc3 = make_float4(0.f, 0.f, 0.f, 0.f);

        #pragma unroll 4
        for (int k = 0; k < CC; k++) {
            const float4 xq = *reinterpret_cast<const float4*>(&xsT[k * ROW + p0]);
            const float4 w  = *reinterpret_cast<const float4*>(&Wb[k * ws]);
            acc0.x = fmaf(xq.x, w.x, acc0.x);
            acc0.y = fmaf(xq.x, w.y, acc0.y);
            acc0.z = fmaf(xq.x, w.z, acc0.z);
            acc0.w = fmaf(xq.x, w.w, acc0.w);
            acc1.x = fmaf(xq.y, w.x, acc1.x);
            acc1.y = fmaf(xq.y, w.y, acc1.y);
            acc1.z = fmaf(xq.y, w.z, acc1.z);
            acc1.w = fmaf(xq.y, w.w, acc1.w);
            acc2.x = fmaf(xq.z, w.x, acc2.x);
            acc2.y = fmaf(xq.z, w.y, acc2.y);
            acc2.z = fmaf(xq.z, w.z, acc2.z);
            acc2.w = fmaf(xq.z, w.w, acc2.w);
            acc3.x = fmaf(xq.w, w.x, acc3.x);
            acc3.y = fmaf(xq.w, w.y, acc3.y);
            acc3.z = fmaf(xq.w, w.z, acc3.z);
            acc3.w = fmaf(xq.w, w.w, acc3.w);
        }
        const float4 bv = *reinterpret_cast<const float4*>(bias + j0);
        acc0.x += bv.x; acc0.y += bv.y; acc0.z += bv.z; acc0.w += bv.w;
        acc1.x += bv.x; acc1.y += bv.y; acc1.z += bv.z; acc1.w += bv.w;
        acc2.x += bv.x; acc2.y += bv.y; acc2.z += bv.z; acc2.w += bv.w;
        acc3.x += bv.x; acc3.y += bv.y; acc3.z += bv.z; acc3.w += bv.w;

        if (is_off) {
            *reinterpret_cast<float4*>(&offs[p0 + 0][j0]) = acc0;
            *reinterpret_cast<float4*>(&offs[p0 + 1][j0]) = acc1;
            *reinterpret_cast<float4*>(&offs[p0 + 2][j0]) = acc2;
            *reinterpret_cast<float4*>(&offs[p0 + 3][j0]) = acc3;
        } else {
            *reinterpret_cast<float4*>(&msk[p0 + 0][j0]) = acc0;
            *reinterpret_cast<float4*>(&msk[p0 + 1][j0]) = acc1;
            *reinterpret_cast<float4*>(&msk[p0 + 2][j0]) = acc2;
            *reinterpret_cast<float4*>(&msk[p0 + 3][j0]) = acc3;
        }
    }
    __syncthreads();

    // ---- phase 2: softmax over the 9 taps per (pixel, group) ----
    if (tid < TILE * GG) {
        const int pp = tid / GG, g = tid % GG;
        float* m = &msk[pp][g * PP];
        float mx = m[0];
        #pragma unroll
        for (int p = 1; p < PP; p++) mx = fmaxf(mx, m[p]);
        float e[PP], s = 0.f;
        #pragma unroll
        for (int p = 0; p < PP; p++) { e[p] = __expf(m[p] - mx); s += e[p]; }
        const float inv = 1.f / s;
        #pragma unroll
        for (int p = 0; p < PP; p++) m[p] = e[p] * inv;
    }
    __syncthreads();

    // ---- phase 2.5: per-(pixel,g,p) packed corner base + mask-folded weights ----
    // (overwrites xsT; safe, xsT is dead after phase 1)
    for (int idx = tid; idx < TILE * NMSK; idx += NTHR) {
        const int pp = idx / NMSK;
        const int gp = idx % NMSK;
        const int p  = gp % PP;
        const float dx = offs[pp][gp * 2 + 0];
        const float dy = offs[pp][gp * 2 + 1];
        // padded coords: px = w + p/3 + dx ; py = h + p%3 + dy
        const float px = (float)(w0 + pp) + (float)(p / 3) + dx;
        const float py = (float)h + (float)(p % 3) + dy;
        const float x0f = floorf(px), y0f = floorf(py);
        const float tx = px - x0f, ty = py - y0f;
        const int ix0 = (int)x0f, iy0 = (int)y0f;
        const float m = msk[pp][gp];

        float w00 = (1.f - tx) * (1.f - ty) * m;
        float w10 = tx * (1.f - ty) * m;
        float w01 = (1.f - tx) * ty * m;
        float w11 = tx * ty * m;
        // zero out-of-range corners (padded coord must be in [1,128])
        const bool vx0 = ((unsigned)(ix0 - 1) < (unsigned)WW);
        const bool vx1 = ((unsigned)(ix0)     < (unsigned)WW);
        const bool vy0 = ((unsigned)(iy0 - 1) < (unsigned)HH);
        const bool vy1 = ((unsigned)(iy0)     < (unsigned)HH);
        if (!(vx0 && vy0)) w00 = 0.f;
        if (!(vx1 && vy0)) w10 = 0.f;
        if (!(vx0 && vy1)) w01 = 0.f;
        if (!(vx1 && vy1)) w11 = 0.f;

        swt[pp][gp]  = make_float4(w00, w10, w01, w11);
        // linear element index of corner (ix0-1, iy0-1); other corners are
        // at constant offsets +CC, +WW*CC, +CC+WW*CC
        slin[pp][gp] = ((b * HH + (iy0 - 1)) * WW + (ix0 - 1)) * CC;
    }
    __syncthreads();

    // ---- phase 3: gather + accumulate. warp = pixel, lane = float4 channel slot ----
    const int c4 = tid & 31;          // float4 slot -> channels [4*c4, 4*c4+3]
    const int g  = c4 >> 3;           // group of this channel slot
    const float4* in4 = reinterpret_cast<const float4*>(in);
    float4* out4 = reinterpret_cast<float4*>(out);

    #pragma unroll
    for (int pass = 0; pass < 4; pass++) {
        const int pp = (tid >> 5) + pass * 8;
        float4 acc = make_float4(0.f, 0.f, 0.f, 0.f);
        #pragma unroll
        for (int p = 0; p < PP; p++) {
            const int gp = g * PP + p;
            const float4 wv = swt[pp][gp];
            const int base = (slin[pp][gp] >> 2) + c4;   // float4 units
            if (wv.x != 0.f) {
                const float4 v = in4[base];
                acc.x = fmaf(wv.x, v.x, acc.x); acc.y = fmaf(wv.x, v.y, acc.y);
                acc.z = fmaf(wv.x, v.z, acc.z); acc.w = fmaf(wv.x, v.w, acc.w);
            }
            if (wv.y != 0.f) {
                const float4 v = in4[base + (CC / 4)];
                acc.x = fmaf(wv.y, v.x, acc.x); acc.y = fmaf(wv.y, v.y, acc.y);
                acc.z = fmaf(wv.y, v.z, acc.z); acc.w = fmaf(wv.y, v.w, acc.w);
            }
            if (wv.z != 0.f) {
                const float4 v = in4[base + (WW * CC / 4)];
                acc.x = fmaf(wv.z, v.x, acc.x); acc.y = fmaf(wv.z, v.y, acc.y);
                acc.z = fmaf(wv.z, v.z, acc.z); acc.w = fmaf(wv.z, v.w, acc.w);
            }
            if (wv.w != 0.f) {
                const float4 v = in4[base + (WW * CC / 4) + (CC / 4)];
                acc.x = fmaf(wv.w, v.x, acc.x); acc.y = fmaf(wv.w, v.y, acc.y);
                acc.z = fmaf(wv.w, v.z, acc.z); acc.w = fmaf(wv.w, v.w, acc.w);
            }
        }
        const size_t o = (((size_t)b * HH + h) * WW + (w0 + pp)) * (CC / 4) + c4;
        out4[o] = acc;
    }
}

extern "C" void kernel_launch(void* const* d_in, const int* in_sizes, int n_in,
                              void* d_out, int out_size) {
    const float* inp   = (const float*)d_in[0];
    const float* Woff  = (const float*)d_in[1];
    const float* boff  = (const float*)d_in[2];
    const float* Wmask = (const float*)d_in[3];
    const float* bmask = (const float*)d_in[4];
    float* out = (float*)d_out;

    const int nblocks = BB * HH * (WW / TILE);   // 4*128*4 = 2048
    dcnv3_fused<<<nblocks, NTHR>>>(inp, Woff, boff, Wmask, bmask, out);
}

// round 6
// speedup vs baseline: 2.1435x; 1.0022x over previous
#include <cuda_runtime.h>

// Problem constants (fixed for this dataset)
#define BB   4
#define CC   128
#define HH   128
#define WW   128
#define GG   4
#define GCH  32      // channels per group
#define PP   9       // K*K taps
#define NOFF 72      // G*P*2
#define NMSK 36      // G*P
#define TILE 32      // pixels per block
#define NTHR 256
#define ROW  36      // xsT row length in floats (32 px + 4 pad, 16B-aligned)

// overlay buffer: phases 0/1 use it as xsT[CC][ROW] (18432 B);
// phases 2.5/3 use it as swt[TILE][NMSK] float4 (18432 B) + slin[TILE][NMSK] int (4608 B)
#define UBUF_BYTES (TILE * NMSK * 16 + TILE * NMSK * 4)   // 23040

__global__ __launch_bounds__(NTHR, 5) void dcnv3_fused(
    const float* __restrict__ in,     // (B,H,W,C) channel-last (view of (B,C,H,W))
    const float* __restrict__ Woff,   // (C, 72) row-major
    const float* __restrict__ boff,   // (72)
    const float* __restrict__ Wmask,  // (C, 36) row-major
    const float* __restrict__ bmask,  // (36)
    float* __restrict__ out)          // (B,H,W,C) channel-last
{
    __shared__ __align__(16) char ubuf[UBUF_BYTES];   // 22.5 KB (xsT | swt+slin)
    __shared__ float offs[TILE][NOFF];                // 9 KB
    __shared__ float msk[TILE][NMSK];                 // 4.5 KB

    float* xsT          = reinterpret_cast<float*>(ubuf);             // [CC][ROW]
    float4 (*swt)[NMSK] = reinterpret_cast<float4(*)[NMSK]>(ubuf);
    int (*slin)[NMSK]   = reinterpret_cast<int(*)[NMSK]>(ubuf + TILE * NMSK * 16);

    const int tid = threadIdx.x;
    const int blk = blockIdx.x;
    const int wt = blk % (WW / TILE);
    const int h  = (blk / (WW / TILE)) % HH;
    const int b  = blk / ((WW / TILE) * HH);
    const int w0 = wt * TILE;

    // ---- phase 0: load 32 pixels' features and store TRANSPOSED into xsT ----
    // lane groups of 4 do a 4x4 register transpose so STS.128 is conflict-free.
    const float4* xbase4 = reinterpret_cast<const float4*>(
        in + (((size_t)b * HH + h) * WW + w0) * CC);
    const int r = tid & 3;   // element/row index inside 4-lane transpose group
    #pragma unroll
    for (int it = 0; it < 4; it++) {
        const int i  = tid + it * NTHR;      // 0..1023
        const int q  = i >> 7;               // pixel quad 0..7
        const int k4 = (i >> 2) & 31;        // channel quad 0..31
        // load: pixel (4q + r), channels 4k4..4k4+3
        float4 v = xbase4[(q * 4 + r) * (CC / 4) + k4];
        float a0 = v.x, a1 = v.y, a2 = v.z, a3 = v.w;
        // 4x4 transpose across lanes (xor 1 then xor 2)
        {
            float s0 = (r & 1) ? a0 : a1;
            float s1 = (r & 1) ? a2 : a3;
            float g0 = __shfl_xor_sync(0xFFFFFFFF, s0, 1);
            float g1 = __shfl_xor_sync(0xFFFFFFFF, s1, 1);
            if (r & 1) { a0 = g0; a2 = g1; } else { a1 = g0; a3 = g1; }
        }
        {
            float u0 = (r & 2) ? a0 : a2;
            float u1 = (r & 2) ? a1 : a3;
            float h0 = __shfl_xor_sync(0xFFFFFFFF, u0, 2);
            float h1 = __shfl_xor_sync(0xFFFFFFFF, u1, 2);
            if (r & 2) { a0 = h0; a1 = h1; } else { a2 = h0; a3 = h1; }
        }
        // now lane holds channel (4*k4 + r) for pixels 4q..4q+3
        *reinterpret_cast<float4*>(&xsT[(4 * k4 + r) * ROW + 4 * q]) =
            make_float4(a0, a1, a2, a3);
    }
    __syncthreads();

    // ---- phase 1: register-tiled matvec. 4 pixels x 4 outputs per thread.
    // jq = tid>>3 (27 j-quads), pg = tid&7 (8 pixel quads).
    // W LDG.128: 4 adjacent j-quads per warp -> ~1 wavefront (broadcast).
    // x LDS.128: 8 pixel quads cover 128 contiguous bytes -> conflict-free.
    if (tid < 216) {
        const int jq = tid >> 3;             // 0..26
        const int pg = tid & 7;              // 0..7
        const int p0 = pg * 4;
        const bool is_off = (jq < 18);
        const int j0 = is_off ? jq * 4 : (jq - 18) * 4;
        const float* Wb = (is_off ? Woff : Wmask) + j0;
        const int ws = is_off ? NOFF : NMSK;     // row stride in floats
        const float* bias = is_off ? boff : bmask;

        float4 acc0 = make_float4(0.f, 0.f, 0.f, 0.f);
        float4 acc1 = make_float4(0.f, 0.f, 0.f, 0.f);
        float4 acc2 = make_float4(0.f, 0.f, 0.f, 0.f);
        float4 acc3 = make_float4(0.f, 0.f, 0.f, 0.f);

        #pragma unroll 4
        for (int k = 0; k < CC; k++) {
            const float4 xq = *reinterpret_cast<const float4*>(&xsT[k * ROW + p0]);
            const float4 w  = *reinterpret_cast<const float4*>(&Wb[k * ws]);
            acc0.x = fmaf(xq.x, w.x, acc0.x);
            acc0.y = fmaf(xq.x, w.y, acc0.y);
            acc0.z = fmaf(xq.x, w.z, acc0.z);
            acc0.w = fmaf(xq.x, w.w, acc0.w);
            acc1.x = fmaf(xq.y, w.x, acc1.x);
            acc1.y = fmaf(xq.y, w.y, acc1.y);
            acc1.z = fmaf(xq.y, w.z, acc1.z);
            acc1.w = fmaf(xq.y, w.w, acc1.w);
            acc2.x = fmaf(xq.z, w.x, acc2.x);
            acc2.y = fmaf(xq.z, w.y, acc2.y);
            acc2.z = fmaf(xq.z, w.z, acc2.z);
            acc2.w = fmaf(xq.z, w.w, acc2.w);
            acc3.x = fmaf(xq.w, w.x, acc3.x);
            acc3.y = fmaf(xq.w, w.y, acc3.y);
            acc3.z = fmaf(xq.w, w.z, acc3.z);
            acc3.w = fmaf(xq.w, w.w, acc3.w);
        }
        const float4 bv = *reinterpret_cast<const float4*>(bias + j0);
        acc0.x += bv.x; acc0.y += bv.y; acc0.z += bv.z; acc0.w += bv.w;
        acc1.x += bv.x; acc1.y += bv.y; acc1.z += bv.z; acc1.w += bv.w;
        acc2.x += bv.x; acc2.y += bv.y; acc2.z += bv.z; acc2.w += bv.w;
        acc3.x += bv.x; acc3.y += bv.y; acc3.z += bv.z; acc3.w += bv.w;

        if (is_off) {
            *reinterpret_cast<float4*>(&offs[p0 + 0][j0]) = acc0;
            *reinterpret_cast<float4*>(&offs[p0 + 1][j0]) = acc1;
            *reinterpret_cast<float4*>(&offs[p0 + 2][j0]) = acc2;
            *reinterpret_cast<float4*>(&offs[p0 + 3][j0]) = acc3;
        } else {
            *reinterpret_cast<float4*>(&msk[p0 + 0][j0]) = acc0;
            *reinterpret_cast<float4*>(&msk[p0 + 1][j0]) = acc1;
            *reinterpret_cast<float4*>(&msk[p0 + 2][j0]) = acc2;
            *reinterpret_cast<float4*>(&msk[p0 + 3][j0]) = acc3;
        }
    }
    __syncthreads();

    // ---- phase 2: softmax over the 9 taps per (pixel, group) ----
    if (tid < TILE * GG) {
        const int pp = tid / GG, g = tid % GG;
        float* m = &msk[pp][g * PP];
        float mx = m[0];
        #pragma unroll
        for (int p = 1; p < PP; p++) mx = fmaxf(mx, m[p]);
        float e[PP], s = 0.f;
        #pragma unroll
        for (int p = 0; p < PP; p++) { e[p] = __expf(m[p] - mx); s += e[p]; }
        const float inv = 1.f / s;
        #pragma unroll
        for (int p = 0; p < PP; p++) m[p] = e[p] * inv;
    }
    __syncthreads();

    // ---- phase 2.5: per-(pixel,g,p) packed corner base + mask-folded weights ----
    // (overwrites xsT; safe, xsT is dead after phase 1)
    for (int idx = tid; idx < TILE * NMSK; idx += NTHR) {
        const int pp = idx / NMSK;
        const int gp = idx % NMSK;
        const int p  = gp % PP;
        const float dx = offs[pp][gp * 2 + 0];
        const float dy = offs[pp][gp * 2 + 1];
        // padded coords: px = w + p/3 + dx ; py = h + p%3 + dy
        const float px = (float)(w0 + pp) + (float)(p / 3) + dx;
        const float py = (float)h + (float)(p % 3) + dy;
        const float x0f = floorf(px), y0f = floorf(py);
        const float tx = px - x0f, ty = py - y0f;
        const int ix0 = (int)x0f, iy0 = (int)y0f;
        const float m = msk[pp][gp];

        float w00 = (1.f - tx) * (1.f - ty) * m;
        float w10 = tx * (1.f - ty) * m;
        float w01 = (1.f - tx) * ty * m;
        float w11 = tx * ty * m;
        // zero out-of-range corners (padded coord must be in [1,128])
        const bool vx0 = ((unsigned)(ix0 - 1) < (unsigned)WW);
        const bool vx1 = ((unsigned)(ix0)     < (unsigned)WW);
        const bool vy0 = ((unsigned)(iy0 - 1) < (unsigned)HH);
        const bool vy1 = ((unsigned)(iy0)     < (unsigned)HH);
        if (!(vx0 && vy0)) w00 = 0.f;
        if (!(vx1 && vy0)) w10 = 0.f;
        if (!(vx0 && vy1)) w01 = 0.f;
        if (!(vx1 && vy1)) w11 = 0.f;

        swt[pp][gp]  = make_float4(w00, w10, w01, w11);
        // linear element index of corner (ix0-1, iy0-1); affine, so corner k's
        // index = slin + const_k is correct whenever corner k is in-bounds
        slin[pp][gp] = ((b * HH + (iy0 - 1)) * WW + (ix0 - 1)) * CC;
    }
    __syncthreads();

    // ---- phase 3: BRANCHLESS gather. warp = pixel, lane = float4 channel slot.
    // wv differs across lanes (4 groups/warp), so branches would diverge;
    // instead SEL the address to 0 (always valid) when the weight is 0 and
    // issue all loads + FMAs unconditionally (0 * finite = 0).
    const int c4 = tid & 31;          // float4 slot -> channels [4*c4, 4*c4+3]
    const int g  = c4 >> 3;           // group of this channel slot
    const float4* in4 = reinterpret_cast<const float4*>(in);
    float4* out4 = reinterpret_cast<float4*>(out);

    #pragma unroll
    for (int pass = 0; pass < 4; pass++) {
        const int pp = (tid >> 5) + pass * 8;
        float4 acc = make_float4(0.f, 0.f, 0.f, 0.f);
        #pragma unroll
        for (int p = 0; p < PP; p++) {
            const int gp = g * PP + p;
            const float4 wv = swt[pp][gp];
            const int base = (slin[pp][gp] >> 2) + c4;   // float4 units
            const int a00 = (wv.x != 0.f) ? base : 0;
            const int a10 = (wv.y != 0.f) ? base + (CC / 4) : 0;
            const int a01 = (wv.z != 0.f) ? base + (WW * CC / 4) : 0;
            const int a11 = (wv.w != 0.f) ? base + (WW * CC / 4) + (CC / 4) : 0;
            const float4 v00 = in4[a00];
            const float4 v10 = in4[a10];
            const float4 v01 = in4[a01];
            const float4 v11 = in4[a11];
            acc.x = fmaf(wv.x, v00.x, acc.x); acc.y = fmaf(wv.x, v00.y, acc.y);
            acc.z = fmaf(wv.x, v00.z, acc.z); acc.w = fmaf(wv.x, v00.w, acc.w);
            acc.x = fmaf(wv.y, v10.x, acc.x); acc.y = fmaf(wv.y, v10.y, acc.y);
            acc.z = fmaf(wv.y, v10.z, acc.z); acc.w = fmaf(wv.y, v10.w, acc.w);
            acc.x = fmaf(wv.z, v01.x, acc.x); acc.y = fmaf(wv.z, v01.y, acc.y);
            acc.z = fmaf(wv.z, v01.z, acc.z); acc.w = fmaf(wv.z, v01.w, acc.w);
            acc.x = fmaf(wv.w, v11.x, acc.x); acc.y = fmaf(wv.w, v11.y, acc.y);
            acc.z = fmaf(wv.w, v11.z, acc.z); acc.w = fmaf(wv.w, v11.w, acc.w);
        }
        const size_t o = (((size_t)b * HH + h) * WW + (w0 + pp)) * (CC / 4) + c4;
        out4[o] = acc;
    }
}

extern "C" void kernel_launch(void* const* d_in, const int* in_sizes, int n_in,
                              void* d_out, int out_size) {
    const float* inp   = (const float*)d_in[0];
    const float* Woff  = (const float*)d_in[1];
    const float* boff  = (const float*)d_in[2];
    const float* Wmask = (const float*)d_in[3];
    const float* bmask = (const float*)d_in[4];
    float* out = (float*)d_out;

    const int nblocks = BB * HH * (WW / TILE);   // 4*128*4 = 2048
    dcnv3_fused<<<nblocks, NTHR>>>(inp, Woff, boff, Wmask, bmask, out);
}